// round 7
// baseline (speedup 1.0000x reference)
#include <cuda_runtime.h>
#include <cuda_fp16.h>
#include <math.h>
#include <stdint.h>

#define BB 512
#define TT 2048
#define DD 20
#define C0 32
#define C1 16
#define CH 256
#define NCHUNK ((BB*TT)/CH)     /* 4096 */
#define NTOT   ((double)(BB)*(double)(TT))

typedef unsigned long long u64;

// ---------------- scratch (device globals; no allocation) ----------------
__device__ uint4  g_h1h[(size_t)NCHUNK * 8 * 2 * 32];  // fp16 h1: 33.5MB
__device__ float  g_Weff[BB * DD * C0];            // [b][d][c]
__device__ float  g_Cb[BB * C0];                   // [b][c]
__device__ float  g_gram[BB * 240];                // [b][tile<15][16]
__device__ float  g_ksum[BB * DD];                 // [b][d]
__device__ double g_stats[96];                     // [0:32) s0 [32:64) q0 [64:80) s1 [80:96) q1
__device__ float4 g_dice0[C0];                     // {mean, rstd, alpha, 1-alpha}
__device__ float4 g_dice1[C1];

#define F4Z make_float4(0.f,0.f,0.f,0.f)
#define F4FMA(acc_,wv_,kk_) {acc_.x=fmaf((kk_),(wv_).x,acc_.x);acc_.y=fmaf((kk_),(wv_).y,acc_.y);acc_.z=fmaf((kk_),(wv_).z,acc_.z);acc_.w=fmaf((kk_),(wv_).w,acc_.w);}
#define F4ADD(acc_,bv_)     {acc_.x+=(bv_).x;acc_.y+=(bv_).y;acc_.z+=(bv_).z;acc_.w+=(bv_).w;}
#define SHRED(vv_) {for(int o_=16;o_>0;o_>>=1){vv_.x+=__shfl_xor_sync(0xffffffffu,vv_.x,o_);vv_.y+=__shfl_xor_sync(0xffffffffu,vv_.y,o_);vv_.z+=__shfl_xor_sync(0xffffffffu,vv_.z,o_);vv_.w+=__shfl_xor_sync(0xffffffffu,vv_.w,o_);}}

// ---- packed f32x2 primitives ----
__device__ __forceinline__ u64 pack2(float lo, float hi) {
    u64 r; asm("mov.b64 %0, {%1, %2};" : "=l"(r) : "f"(lo), "f"(hi)); return r;
}
__device__ __forceinline__ void unpack2(u64 v, float& lo, float& hi) {
    asm("mov.b64 {%0, %1}, %2;" : "=f"(lo), "=f"(hi) : "l"(v));
}
__device__ __forceinline__ void fma2(u64& acc, u64 a, u64 b) {
    asm("fma.rn.f32x2 %0, %1, %2, %0;" : "+l"(acc) : "l"(a), "l"(b));
}
__device__ __forceinline__ void add2(u64& acc, u64 a) {
    asm("add.rn.f32x2 %0, %1, %0;" : "+l"(acc) : "l"(a));
}
__device__ __forceinline__ uint32_t h2p(u64 v) {
    float lo, hi; unpack2(v, lo, hi);
    union { __half2 h; uint32_t u; } cv;
    cv.h = __floats2half2_rn(lo, hi);
    return cv.u;
}
__device__ __forceinline__ float2 upkh(uint32_t u) {
    union { __half2 h; uint32_t u; } cv;
    cv.u = u;
    return __half22float2(cv.h);
}

__device__ __forceinline__ float dice_f(float x, float4 pr) {
    float xn = (x - pr.x) * pr.y;
    float p  = 1.0f / (1.0f + __expf(-xn));
    return x * (pr.z + p * pr.w);
}

// stage one 256x20 key chunk into padded smem (row stride 21 -> conflict-free scalar reads)
__device__ __forceinline__ void stage_keys(float* sK, const float* __restrict__ keys,
                                           size_t chunk, int tid) {
    const float4* src = (const float4*)(keys + chunk * (size_t)(CH * DD));
#pragma unroll
    for (int i = 0; i < 5; i++) {
        float4 t = src[tid + i * CH];
        int f = tid + i * CH;
        int r = f / 5;
        int c = (f - r * 5) * 4;
        float* p = &sK[r * 21 + c];
        p[0] = t.x; p[1] = t.y; p[2] = t.z; p[3] = t.w;
    }
}

// ---------------- K0: per-batch folded weights + zero accumulators ----------------
__global__ void k_prep(const float* __restrict__ q, const float* __restrict__ W0,
                       const float* __restrict__ b0, float* __restrict__ out) {
    int b = blockIdx.x;
    int c = threadIdx.x;              // 32 threads
    if (b == 0) {
        for (int i = c; i < 96; i += 32) g_stats[i] = 0.0;
    }
    int gid = b * 32 + c;
    if (gid < BB * DD) out[gid] = 0.0f;

    float acc = b0[c];
#pragma unroll
    for (int d = 0; d < DD; d++) {
        float qd = q[b * DD + d];
        float wA = W0[(d)          * C0 + c];
        float wB = W0[(DD + d)     * C0 + c];
        float wC = W0[(2 * DD + d) * C0 + c];
        float wD = W0[(3 * DD + d) * C0 + c];
        g_Weff[(b * DD + d) * C0 + c] = wB - wC + qd * wD;
        acc += qd * (wA + wC);
    }
    g_Cb[b * C0 + c] = acc;
}

// ---------------- KG: per-batch Gram matrix (4x4 tiles, lower-tri) + column sums ----------------
__global__ void __launch_bounds__(256) k_gram(const float* __restrict__ keys) {
    int b   = blockIdx.x;             // 512 blocks, one per batch
    int tid = threadIdx.x;
    int tile = tid & 15;              // 0..14 = gram tiles, 15 = column sums
    int copy = tid >> 4;              // 16 copies, rows r == copy (mod 16)

    __shared__ float4 sK4[CH * 5];    // 256 rows x 5 float4 (stride 20, aligned)

    // tile -> (ti, tj), lower triangular incl diagonal
    int ti = 0, tj = 0;
    { int tt = tile < 15 ? tile : 0;
      for (int rr = 0; rr < 5; rr++) { if (tt <= rr) { ti = rr; tj = tt; break; } tt -= rr + 1; } }

    float4 acc0=F4Z, acc1=F4Z, acc2=F4Z, acc3=F4Z;      // 4x4 gram tile rows
    float4 sm0=F4Z, sm1=F4Z, sm2=F4Z, sm3=F4Z, sm4=F4Z; // column sums (tile 15)

    const float4* src = (const float4*)(keys + (size_t)b * TT * DD);
    for (int ch = 0; ch < 8; ch++) {
        __syncthreads();
#pragma unroll
        for (int i = 0; i < 5; i++) sK4[tid * 5 + i] = src[(size_t)ch * 1280 + tid * 5 + i];
        __syncthreads();

        if (tile < 15) {
#pragma unroll
            for (int it = 0; it < 16; it++) {
                int r = it * 16 + copy;
                float4 ki = sK4[r * 5 + ti];
                float4 kj = sK4[r * 5 + tj];
                F4FMA(acc0, kj, ki.x); F4FMA(acc1, kj, ki.y);
                F4FMA(acc2, kj, ki.z); F4FMA(acc3, kj, ki.w);
            }
        } else {
#pragma unroll
            for (int it = 0; it < 16; it++) {
                int r = it * 16 + copy;
                F4ADD(sm0, sK4[r*5+0]); F4ADD(sm1, sK4[r*5+1]); F4ADD(sm2, sK4[r*5+2]);
                F4ADD(sm3, sK4[r*5+3]); F4ADD(sm4, sK4[r*5+4]);
            }
        }
    }

    // reduce over 16 copies via smem (reuse sK4 space: 5120 floats available)
    __syncthreads();
    float* red = (float*)sK4;
    const int SUMOFF = 240 * 16;      // 3840
    if (tile < 15) {
        int base = tile * 16;
        red[(base+ 0)*16+copy]=acc0.x; red[(base+ 1)*16+copy]=acc0.y; red[(base+ 2)*16+copy]=acc0.z; red[(base+ 3)*16+copy]=acc0.w;
        red[(base+ 4)*16+copy]=acc1.x; red[(base+ 5)*16+copy]=acc1.y; red[(base+ 6)*16+copy]=acc1.z; red[(base+ 7)*16+copy]=acc1.w;
        red[(base+ 8)*16+copy]=acc2.x; red[(base+ 9)*16+copy]=acc2.y; red[(base+10)*16+copy]=acc2.z; red[(base+11)*16+copy]=acc2.w;
        red[(base+12)*16+copy]=acc3.x; red[(base+13)*16+copy]=acc3.y; red[(base+14)*16+copy]=acc3.z; red[(base+15)*16+copy]=acc3.w;
    } else {
        red[SUMOFF+( 0)*16+copy]=sm0.x; red[SUMOFF+( 1)*16+copy]=sm0.y; red[SUMOFF+( 2)*16+copy]=sm0.z; red[SUMOFF+( 3)*16+copy]=sm0.w;
        red[SUMOFF+( 4)*16+copy]=sm1.x; red[SUMOFF+( 5)*16+copy]=sm1.y; red[SUMOFF+( 6)*16+copy]=sm1.z; red[SUMOFF+( 7)*16+copy]=sm1.w;
        red[SUMOFF+( 8)*16+copy]=sm2.x; red[SUMOFF+( 9)*16+copy]=sm2.y; red[SUMOFF+(10)*16+copy]=sm2.z; red[SUMOFF+(11)*16+copy]=sm2.w;
        red[SUMOFF+(12)*16+copy]=sm3.x; red[SUMOFF+(13)*16+copy]=sm3.y; red[SUMOFF+(14)*16+copy]=sm3.z; red[SUMOFF+(15)*16+copy]=sm3.w;
        red[SUMOFF+(16)*16+copy]=sm4.x; red[SUMOFF+(17)*16+copy]=sm4.y; red[SUMOFF+(18)*16+copy]=sm4.z; red[SUMOFF+(19)*16+copy]=sm4.w;
    }
    __syncthreads();
    if (tid < 240) {
        float s = 0.f;
#pragma unroll
        for (int c2 = 0; c2 < 16; c2++) s += red[tid * 16 + c2];
        g_gram[b * 240 + tid] = s;
    }
    if (tid < DD) {
        float s = 0.f;
#pragma unroll
        for (int c2 = 0; c2 < 16; c2++) s += red[SUMOFF + tid * 16 + c2];
        g_ksum[b * DD + tid] = s;
    }
}

// ---------------- KS0: analytic layer-0 stats from Gram ----------------
__global__ void k_stats0() {
    int b = blockIdx.x;               // 512
    int c = threadIdx.x;              // 32 channels
    float w[DD];
#pragma unroll
    for (int d = 0; d < DD; d++) w[d] = g_Weff[(b * DD + d) * C0 + c];

    const int TI[15] = {0,1,1,2,2,2,3,3,3,3,4,4,4,4,4};
    const int TJ[15] = {0,0,1,0,1,2,0,1,2,3,0,1,2,3,4};
    const float* G = &g_gram[b * 240];

    float wgw = 0.f;
#pragma unroll
    for (int t = 0; t < 15; t++) {
        int ti = TI[t], tj = TJ[t];
        float part = 0.f;
#pragma unroll
        for (int a = 0; a < 4; a++)
#pragma unroll
            for (int cc = 0; cc < 4; cc++)
                part = fmaf(w[ti*4+a] * G[t*16 + a*4 + cc], w[tj*4+cc], part);
        wgw += (ti == tj) ? part : 2.f * part;
    }
    float dot = 0.f;
#pragma unroll
    for (int d = 0; d < DD; d++) dot = fmaf(w[d], g_ksum[b * DD + d], dot);

    float cb = g_Cb[b * C0 + c];
    float msum = dot + 2048.f * cb;
    float qsum = wgw + 2.f * cb * dot + 2048.f * cb * cb;
    atomicAdd(&g_stats[c], (double)msum);
    atomicAdd(&g_stats[32 + c], (double)qsum);
}

// ---------------- K2: finalize layer-0 batchnorm ----------------
__global__ void k_fin0(const float* __restrict__ a0) {
    int c = threadIdx.x;  // 32
    double m = g_stats[c] / NTOT;
    double v = g_stats[32 + c] / NTOT - m * m;
    float rstd = (float)(1.0 / sqrt(v + 1e-9));
    float al = a0[c];
    g_dice0[c] = make_float4((float)m, rstd, al, 1.0f - al);
}

// ---------------- KM: fused h0 (in-register) -> dice0 -> h1; store fp16 h1 + stats ----------------
#define H1STEP(xs_, d_) { float hd_ = dice_f((xs_), sD0[(d_)]); \
    u64 hdd_ = pack2(hd_, hd_); ulonglong2 w_; \
    w_=sW1_2[(d_)*4+0]; fma2(b0,w_.x,hdd_); fma2(b1,w_.y,hdd_); \
    w_=sW1_2[(d_)*4+1]; fma2(b2,w_.x,hdd_); fma2(b3,w_.y,hdd_); \
    w_=sW1_2[(d_)*4+2]; fma2(b4,w_.x,hdd_); fma2(b5,w_.y,hdd_); \
    w_=sW1_2[(d_)*4+3]; fma2(b6,w_.x,hdd_); fma2(b7,w_.y,hdd_); }
#define HMID(ai_, i_) { float f0_, f1_; unpack2((ai_), f0_, f1_); \
    H1STEP(f0_, 2*(i_)) H1STEP(f1_, 2*(i_)+1) }

__global__ void __launch_bounds__(CH, 2) k_mid(const float* __restrict__ keys,
                                               const float* __restrict__ W1,
                                               const float* __restrict__ b1) {
    int blk = blockIdx.x;             // 1024 blocks: 2 per batch, 4 chunks each
    int b   = blk >> 1;
    int ck0 = (blk & 1) * 4;
    int tid = threadIdx.x;
    int lane = tid & 31, warp = tid >> 5;

    __shared__ float4 sW[DD * 8];     // Weff [d][c4]
    __shared__ float4 sC[8];
    __shared__ float4 sW1[C0 * 4];
    __shared__ float4 sB1[4];
    __shared__ float4 sD0[C0];
    __shared__ float  sK[CH * 21];
    __shared__ float4 sRed[8 * 8];

    for (int i = tid; i < DD * 8; i += CH)
        sW[i] = ((const float4*)(&g_Weff[b * DD * C0]))[i];
    if (tid < 8)  sC[tid] = ((const float4*)(&g_Cb[b * C0]))[tid];
    if (tid >= CH - 128 && tid < CH - 128 + C0 * 4) sW1[tid - (CH-128)] = ((const float4*)W1)[tid - (CH-128)];
    if (tid < 4)  sB1[tid] = ((const float4*)b1)[tid];
    if (tid >= 64 && tid < 64 + C0) sD0[tid - 64] = g_dice0[tid - 64];

    const ulonglong2* sW2   = (const ulonglong2*)sW;
    const ulonglong2* sC2   = (const ulonglong2*)sC;
    const ulonglong2* sW1_2 = (const ulonglong2*)sW1;
    const ulonglong2* sB1_2 = (const ulonglong2*)sB1;

    u64 s0=0,s1=0,s2=0,s3=0,s4=0,s5=0,s6=0,s7=0;
    u64 q0=0,q1=0,q2=0,q3=0,q4=0,q5=0,q6=0,q7=0;

    for (int lc = 0; lc < 4; lc++) {
        size_t chunk = (size_t)b * 8 + ck0 + lc;
        __syncthreads();
        stage_keys(sK, keys, chunk, tid);
        __syncthreads();

        // ---- layer 0 in registers ----
        u64 a0,a1,a2,a3,a4,a5,a6,a7,a8,a9,a10,a11,a12,a13,a14,a15;
        { ulonglong2 t;
          t=sC2[0]; a0 =t.x; a1 =t.y;  t=sC2[1]; a2 =t.x; a3 =t.y;
          t=sC2[2]; a4 =t.x; a5 =t.y;  t=sC2[3]; a6 =t.x; a7 =t.y;
          t=sC2[4]; a8 =t.x; a9 =t.y;  t=sC2[5]; a10=t.x; a11=t.y;
          t=sC2[6]; a12=t.x; a13=t.y;  t=sC2[7]; a14=t.x; a15=t.y; }
#pragma unroll
        for (int d = 0; d < DD; d++) {
            float kd = sK[tid * 21 + d];
            u64 kdd = pack2(kd, kd);
            ulonglong2 w;
            w=sW2[d*8+0]; fma2(a0 ,w.x,kdd); fma2(a1 ,w.y,kdd);
            w=sW2[d*8+1]; fma2(a2 ,w.x,kdd); fma2(a3 ,w.y,kdd);
            w=sW2[d*8+2]; fma2(a4 ,w.x,kdd); fma2(a5 ,w.y,kdd);
            w=sW2[d*8+3]; fma2(a6 ,w.x,kdd); fma2(a7 ,w.y,kdd);
            w=sW2[d*8+4]; fma2(a8 ,w.x,kdd); fma2(a9 ,w.y,kdd);
            w=sW2[d*8+5]; fma2(a10,w.x,kdd); fma2(a11,w.y,kdd);
            w=sW2[d*8+6]; fma2(a12,w.x,kdd); fma2(a13,w.y,kdd);
            w=sW2[d*8+7]; fma2(a14,w.x,kdd); fma2(a15,w.y,kdd);
        }

        // ---- dice0 + layer 1 ----
        u64 b0,b1,b2,b3,b4,b5,b6,b7;
        { ulonglong2 t;
          t=sB1_2[0]; b0=t.x; b1=t.y;  t=sB1_2[1]; b2=t.x; b3=t.y;
          t=sB1_2[2]; b4=t.x; b5=t.y;  t=sB1_2[3]; b6=t.x; b7=t.y; }
        HMID(a0 , 0) HMID(a1 , 1) HMID(a2 , 2) HMID(a3 , 3)
        HMID(a4 , 4) HMID(a5 , 5) HMID(a6 , 6) HMID(a7 , 7)
        HMID(a8 , 8) HMID(a9 , 9) HMID(a10,10) HMID(a11,11)
        HMID(a12,12) HMID(a13,13) HMID(a14,14) HMID(a15,15)

        uint4 pA = make_uint4(h2p(b0), h2p(b1), h2p(b2), h2p(b3));
        uint4 pB = make_uint4(h2p(b4), h2p(b5), h2p(b6), h2p(b7));
        uint4* dst = &g_h1h[chunk * 512 + warp * 64];
        __stcs(&dst[0*32+lane], pA); __stcs(&dst[1*32+lane], pB);

        add2(s0,b0); add2(s1,b1); add2(s2,b2); add2(s3,b3);
        add2(s4,b4); add2(s5,b5); add2(s6,b6); add2(s7,b7);
        fma2(q0,b0,b0); fma2(q1,b1,b1); fma2(q2,b2,b2); fma2(q3,b3,b3);
        fma2(q4,b4,b4); fma2(q5,b5,b5); fma2(q6,b6,b6); fma2(q7,b7,b7);
    }

    float4 S0,S1,S2,S3, Q0,Q1,Q2,Q3;
    unpack2(s0,S0.x,S0.y); unpack2(s1,S0.z,S0.w);  unpack2(s2,S1.x,S1.y); unpack2(s3,S1.z,S1.w);
    unpack2(s4,S2.x,S2.y); unpack2(s5,S2.z,S2.w);  unpack2(s6,S3.x,S3.y); unpack2(s7,S3.z,S3.w);
    unpack2(q0,Q0.x,Q0.y); unpack2(q1,Q0.z,Q0.w);  unpack2(q2,Q1.x,Q1.y); unpack2(q3,Q1.z,Q1.w);
    unpack2(q4,Q2.x,Q2.y); unpack2(q5,Q2.z,Q2.w);  unpack2(q6,Q3.x,Q3.y); unpack2(q7,Q3.z,Q3.w);

    SHRED(S0); SHRED(S1); SHRED(S2); SHRED(S3);
    SHRED(Q0); SHRED(Q1); SHRED(Q2); SHRED(Q3);
    if (lane == 0) {
        float4* r = &sRed[warp * 8];
        r[0]=S0; r[1]=S1; r[2]=S2; r[3]=S3;
        r[4]=Q0; r[5]=Q1; r[6]=Q2; r[7]=Q3;
    }
    __syncthreads();
    if (tid < 32) {
        const float* rf = (const float*)sRed;
        float s = 0.f;
#pragma unroll
        for (int w = 0; w < 8; w++) s += rf[w * 32 + tid];
        atomicAdd(&g_stats[64 + tid], (double)s);
    }
}

// ---------------- K4: finalize layer-1 batchnorm ----------------
__global__ void k_fin1(const float* __restrict__ a1) {
    int c = threadIdx.x;  // 16
    double m = g_stats[64 + c] / NTOT;
    double v = g_stats[80 + c] / NTOT - m * m;
    float rstd = (float)(1.0 / sqrt(v + 1e-9));
    float al = a1[c];
    g_dice1[c] = make_float4((float)m, rstd, al, 1.0f - al);
}

// ---------------- K5: score = dice1(h1)@wk + bk; out[b] += score * keys ----------------
__global__ void __launch_bounds__(CH) k_out(const float* __restrict__ keys,
                                            const float* __restrict__ wk,
                                            const float* __restrict__ bk,
                                            float* __restrict__ out) {
    int blk = blockIdx.x;             // 1024: 2 blocks per batch
    int b   = blk >> 1;
    int ck0 = (blk & 1) * 4;
    int tid = threadIdx.x;
    int lane = tid & 31, warp = tid >> 5;

    __shared__ float  sK[CH * 21];
    __shared__ float4 sD1[C1];
    __shared__ float4 sWk4[4];
    __shared__ float  sBk;
    __shared__ float4 sRed[8 * 5];

    if (tid < C1) sD1[tid] = g_dice1[tid];
    if (tid < 4)  sWk4[tid] = ((const float4*)wk)[tid];
    if (tid == 0) sBk = bk[0];

    float4 A0=F4Z,A1=F4Z,A2=F4Z,A3=F4Z,A4=F4Z;

    for (int lc = 0; lc < 4; lc++) {
        size_t chunk = (size_t)b * 8 + ck0 + lc;
        const uint4* hb = &g_h1h[chunk * 512 + warp * 64];
        uint4 u0 = __ldcs(&hb[0*32+lane]);
        uint4 u1 = __ldcs(&hb[1*32+lane]);

        __syncthreads();
        stage_keys(sK, keys, chunk, tid);
        __syncthreads();

        float score = sBk;
        {
            float2 f;
            f = upkh(u0.x);
            score = fmaf(dice_f(f.x, sD1[ 0]), sWk4[0].x, score);
            score = fmaf(dice_f(f.y, sD1[ 1]), sWk4[0].y, score);
            f = upkh(u0.y);
            score = fmaf(dice_f(f.x, sD1[ 2]), sWk4[0].z, score);
            score = fmaf(dice_f(f.y, sD1[ 3]), sWk4[0].w, score);
            f = upkh(u0.z);
            score = fmaf(dice_f(f.x, sD1[ 4]), sWk4[1].x, score);
            score = fmaf(dice_f(f.y, sD1[ 5]), sWk4[1].y, score);
            f = upkh(u0.w);
            score = fmaf(dice_f(f.x, sD1[ 6]), sWk4[1].z, score);
            score = fmaf(dice_f(f.y, sD1[ 7]), sWk4[1].w, score);
            f = upkh(u1.x);
            score = fmaf(dice_f(f.x, sD1[ 8]), sWk4[2].x, score);
            score = fmaf(dice_f(f.y, sD1[ 9]), sWk4[2].y, score);
            f = upkh(u1.y);
            score = fmaf(dice_f(f.x, sD1[10]), sWk4[2].z, score);
            score = fmaf(dice_f(f.y, sD1[11]), sWk4[2].w, score);
            f = upkh(u1.z);
            score = fmaf(dice_f(f.x, sD1[12]), sWk4[3].x, score);
            score = fmaf(dice_f(f.y, sD1[13]), sWk4[3].y, score);
            f = upkh(u1.w);
            score = fmaf(dice_f(f.x, sD1[14]), sWk4[3].z, score);
            score = fmaf(dice_f(f.y, sD1[15]), sWk4[3].w, score);
        }

        const float* kr = &sK[tid * 21];
        A0.x=fmaf(score,kr[0],A0.x);  A0.y=fmaf(score,kr[1],A0.y);
        A0.z=fmaf(score,kr[2],A0.z);  A0.w=fmaf(score,kr[3],A0.w);
        A1.x=fmaf(score,kr[4],A1.x);  A1.y=fmaf(score,kr[5],A1.y);
        A1.z=fmaf(score,kr[6],A1.z);  A1.w=fmaf(score,kr[7],A1.w);
        A2.x=fmaf(score,kr[8],A2.x);  A2.y=fmaf(score,kr[9],A2.y);
        A2.z=fmaf(score,kr[10],A2.z); A2.w=fmaf(score,kr[11],A2.w);
        A3.x=fmaf(score,kr[12],A3.x); A3.y=fmaf(score,kr[13],A3.y);
        A3.z=fmaf(score,kr[14],A3.z); A3.w=fmaf(score,kr[15],A3.w);
        A4.x=fmaf(score,kr[16],A4.x); A4.y=fmaf(score,kr[17],A4.y);
        A4.z=fmaf(score,kr[18],A4.z); A4.w=fmaf(score,kr[19],A4.w);
    }

    SHRED(A0); SHRED(A1); SHRED(A2); SHRED(A3); SHRED(A4);
    if (lane == 0) {
        float4* r = &sRed[warp * 5];
        r[0]=A0; r[1]=A1; r[2]=A2; r[3]=A3; r[4]=A4;
    }
    __syncthreads();
    if (tid < DD) {
        const float* rf = (const float*)sRed;
        float s = 0.f;
#pragma unroll
        for (int w = 0; w < 8; w++) s += rf[w * 20 + tid];
        atomicAdd(&out[b * DD + tid], s);
    }
}

// ---------------- launch ----------------
extern "C" void kernel_launch(void* const* d_in, const int* in_sizes, int n_in,
                              void* d_out, int out_size) {
    const float* keys = (const float*)d_in[0];
    const float* q    = (const float*)d_in[1];
    /* d_in[2] = mask: dead in the reference (unmasked scores are used) */
    const float* W0   = (const float*)d_in[3];
    const float* b0   = (const float*)d_in[4];
    const float* a0   = (const float*)d_in[5];
    const float* W1   = (const float*)d_in[6];
    const float* b1   = (const float*)d_in[7];
    const float* a1   = (const float*)d_in[8];
    const float* wk   = (const float*)d_in[9];
    const float* bk   = (const float*)d_in[10];
    float* out = (float*)d_out;

    k_prep  <<<BB, 32>>>(q, W0, b0, out);
    k_gram  <<<BB, 256>>>(keys);
    k_stats0<<<BB, 32>>>();
    k_fin0  <<<1, 32>>>(a0);
    k_mid   <<<1024, CH>>>(keys, W1, b1);
    k_fin1  <<<1, 16>>>(a1);
    k_out   <<<1024, CH>>>(keys, wk, bk, out);
}